// round 11
// baseline (speedup 1.0000x reference)
#include <cuda_runtime.h>
#include <cuda_bf16.h>
#include <stdint.h>

#define T_TOK 8192
#define D_DIM 1024
#define E_EXP 8
#define F_DIM 512
#define NPAIR (T_TOK * 2)

// ---------------- device scratch (proven footprint ~101MB) ----------------
__device__ int   g_topk_idx[NPAIR];
__device__ float g_topk_p[NPAIR];
__device__ int   g_cnt[E_EXP];
__device__ int   g_off[E_EXP];
__device__ int   g_cur[E_EXP];
__device__ int   g_pair_token[NPAIR];
__device__ int   g_pair_pos[NPAIR];
__device__ __align__(256) __nv_bfloat16 g_H_hi[(size_t)(NPAIR + 128) * F_DIM];
__device__ __align__(256) __nv_bfloat16 g_H_lo[(size_t)(NPAIR + 128) * F_DIM];
__device__ float g_O[(size_t)NPAIR * D_DIM];

// ---------------- helpers ----------------
__device__ __forceinline__ uint32_t smem_u32(const void* p) {
    uint32_t a;
    asm("{ .reg .u64 t; cvta.to.shared.u64 t, %1; cvt.u32.u64 %0, t; }"
        : "=r"(a) : "l"(p));
    return a;
}
__device__ __forceinline__ void mma16816(float* c, const uint32_t* a, const uint32_t* b) {
    asm volatile(
        "mma.sync.aligned.m16n8k16.row.col.f32.bf16.bf16.f32 "
        "{%0,%1,%2,%3}, {%4,%5,%6,%7}, {%8,%9}, {%0,%1,%2,%3};"
        : "+f"(c[0]), "+f"(c[1]), "+f"(c[2]), "+f"(c[3])
        : "r"(a[0]), "r"(a[1]), "r"(a[2]), "r"(a[3]), "r"(b[0]), "r"(b[1]));
}
__device__ __forceinline__ void ldsm4(uint32_t* r, uint32_t addr) {
    asm volatile("ldmatrix.sync.aligned.m8n8.x4.shared.b16 {%0,%1,%2,%3}, [%4];"
        : "=r"(r[0]), "=r"(r[1]), "=r"(r[2]), "=r"(r[3]) : "r"(addr));
}
__device__ __forceinline__ void split2(float a, float b, uint32_t* hi, uint32_t* lo) {
    __nv_bfloat162 h = __float22bfloat162_rn(make_float2(a, b));
    float2 hf = __bfloat1622float2(h);
    __nv_bfloat162 l = __float22bfloat162_rn(make_float2(a - hf.x, b - hf.y));
    *hi = *reinterpret_cast<uint32_t*>(&h);
    *lo = *reinterpret_cast<uint32_t*>(&l);
}
__device__ __forceinline__ void split4(float4 v, uint32_t* hi2, uint32_t* lo2) {
    split2(v.x, v.y, hi2 + 0, lo2 + 0);
    split2(v.z, v.w, hi2 + 1, lo2 + 1);
}

// ---------------- small kernels (proven) ----------------
__global__ void init_kernel() {
    if (threadIdx.x < E_EXP) g_cnt[threadIdx.x] = 0;
}

__global__ void router_kernel(const float* __restrict__ x,
                              const float* __restrict__ wr) {
    int t = blockIdx.x;
    int tid = threadIdx.x;
    float acc[E_EXP];
#pragma unroll
    for (int e = 0; e < E_EXP; e++) acc[e] = 0.f;
    const float* xr = x + (size_t)t * D_DIM;
    for (int i = tid; i < D_DIM; i += 128) {
        float xv = xr[i];
#pragma unroll
        for (int e = 0; e < E_EXP; e++) acc[e] += xv * wr[e * D_DIM + i];
    }
    __shared__ float sh[E_EXP][128];
#pragma unroll
    for (int e = 0; e < E_EXP; e++) sh[e][tid] = acc[e];
    __syncthreads();
    for (int s = 64; s > 0; s >>= 1) {
        if (tid < s) {
#pragma unroll
            for (int e = 0; e < E_EXP; e++) sh[e][tid] += sh[e][tid + s];
        }
        __syncthreads();
    }
    if (tid == 0) {
        float l[E_EXP];
#pragma unroll
        for (int e = 0; e < E_EXP; e++) l[e] = sh[e][0];
        int i1 = 0;
#pragma unroll
        for (int e = 1; e < E_EXP; e++) if (l[e] > l[i1]) i1 = e;
        int i2 = (i1 == 0) ? 1 : 0;
#pragma unroll
        for (int e = 0; e < E_EXP; e++) if (e != i1 && l[e] > l[i2]) i2 = e;
        float ex = __expf(l[i2] - l[i1]);
        float inv = 1.f / (1.f + ex);
        g_topk_idx[t * 2 + 0] = i1; g_topk_p[t * 2 + 0] = inv;
        g_topk_idx[t * 2 + 1] = i2; g_topk_p[t * 2 + 1] = ex * inv;
        atomicAdd(&g_cnt[i1], 1);
        atomicAdd(&g_cnt[i2], 1);
    }
}

__global__ void prefix_kernel() {
    if (threadIdx.x == 0) {
        int acc = 0;
        for (int e = 0; e < E_EXP; e++) { g_off[e] = acc; g_cur[e] = acc; acc += g_cnt[e]; }
    }
}

__global__ void scatter_kernel() {
    int t = blockIdx.x * blockDim.x + threadIdx.x;
    if (t >= T_TOK) return;
#pragma unroll
    for (int k = 0; k < 2; k++) {
        int e = g_topk_idx[t * 2 + k];
        int pos = atomicAdd(&g_cur[e], 1);
        g_pair_token[pos] = t;
        g_pair_pos[t * 2 + k] = pos;
    }
}

// smem: 128 rows x 16 bf16 per K-stage, rows padded to 24 shorts, DOUBLE buffered.
// 4 arrays x [2][128][24] shorts = 49152 B (proven R10).
#define PADK 24
#define BUFB (128 * PADK * 2)

// ---------------- GEMM1: H = silu(X Wg) * (X Wu) ----------------
__global__ void __launch_bounds__(256) gemm1_mma(const float* __restrict__ x,
                                                 const float* __restrict__ wg,
                                                 const float* __restrict__ wu) {
    int e = blockIdx.z;
    int cnt = g_cnt[e];
    int m0 = blockIdx.y * 128;
    if (m0 >= cnt) return;
    int base = g_off[e];
    int f0 = blockIdx.x * 64;

    __shared__ unsigned short As_h[2][128][PADK], As_l[2][128][PADK];
    __shared__ unsigned short Bs_h[2][128][PADK], Bs_l[2][128][PADK];

    int tid = threadIdx.x;
    int lid = tid & 31, wid = tid >> 5;
    int wm = wid >> 1, wn = wid & 1;

    uint32_t aH = smem_u32(As_h), aL = smem_u32(As_l);
    uint32_t bH = smem_u32(Bs_h), bL = smem_u32(Bs_l);

    int grp = lid >> 3, lr = lid & 7;
    uint32_t aofs = (uint32_t)(((wm * 32 + (grp & 1) * 8 + lr) * PADK + (grp >> 1) * 8) * 2);
    uint32_t bofs = (uint32_t)(((wn * 32 + (grp >> 1) * 8 + lr) * PADK + (grp & 1) * 8) * 2);

    float acc_g[2][4][4], acc_u[2][4][4];
#pragma unroll
    for (int a = 0; a < 2; a++)
#pragma unroll
        for (int b = 0; b < 4; b++)
#pragma unroll
            for (int c = 0; c < 4; c++) { acc_g[a][b][c] = 0.f; acc_u[a][b][c] = 0.f; }

    int row0 = tid >> 1, kh8 = (tid & 1) * 8;
    int am = m0 + row0;
    int mytok = g_pair_token[base + ((am < cnt) ? am : 0)];
    const float* asrc = x + (size_t)mytok * D_DIM + kh8;
    size_t eoff = (size_t)e * D_DIM * F_DIM;
    const float* bsrc = ((row0 < 64) ? wg : wu) + eoff + (f0 + (row0 & 63));

    // two-slot register prefetch (distance 2)
    float4 apf[2][2];
    float  bpf[2][8];
    const int NS = D_DIM / 16;   // 64 stages

#pragma unroll
    for (int p = 0; p < 2; ++p) {
        int kp = p * 16;
        apf[p][0] = *(const float4*)(asrc + kp);
        apf[p][1] = *(const float4*)(asrc + kp + 4);
#pragma unroll
        for (int j = 0; j < 8; ++j) bpf[p][j] = bsrc[(size_t)(kp + kh8 + j) * F_DIM];
    }

    for (int s = 0; s < NS; ++s) {
        int sl = s & 1;
        uint32_t ah4[4], al4[4], bh4[4], bl4[4];
        split4(apf[sl][0], ah4 + 0, al4 + 0);
        split4(apf[sl][1], ah4 + 2, al4 + 2);
        split2(bpf[sl][0], bpf[sl][1], bh4 + 0, bl4 + 0);
        split2(bpf[sl][2], bpf[sl][3], bh4 + 1, bl4 + 1);
        split2(bpf[sl][4], bpf[sl][5], bh4 + 2, bl4 + 2);
        split2(bpf[sl][6], bpf[sl][7], bh4 + 3, bl4 + 3);
        *(uint4*)&As_h[sl][row0][kh8] = *(uint4*)ah4;
        *(uint4*)&As_l[sl][row0][kh8] = *(uint4*)al4;
        *(uint4*)&Bs_h[sl][row0][kh8] = *(uint4*)bh4;
        *(uint4*)&Bs_l[sl][row0][kh8] = *(uint4*)bl4;
        __syncthreads();

        // refill slot sl for stage s+2 (consumed two stages from now)
        if (s + 2 < NS) {
            int kn = (s + 2) * 16;
            apf[sl][0] = *(const float4*)(asrc + kn);
            apf[sl][1] = *(const float4*)(asrc + kn + 4);
#pragma unroll
            for (int j = 0; j < 8; ++j) bpf[sl][j] = bsrc[(size_t)(kn + kh8 + j) * F_DIM];
        }

        uint32_t bufo = (uint32_t)(sl * BUFB);
        uint32_t ah[2][4], al[2][4];
#pragma unroll
        for (int mi = 0; mi < 2; ++mi) {
            uint32_t ao = bufo + aofs + (uint32_t)(mi * 16 * PADK * 2);
            ldsm4(ah[mi], aH + ao);
            ldsm4(al[mi], aL + ao);
        }
#pragma unroll
        for (int jj = 0; jj < 2; ++jj) {
            uint32_t bo = bufo + bofs + (uint32_t)(jj * 16 * PADK * 2);
            uint32_t gh[4], gl[4], uh[4], ul[4];
            ldsm4(gh, bH + bo);
            ldsm4(gl, bL + bo);
            ldsm4(uh, bH + bo + 64 * PADK * 2);
            ldsm4(ul, bL + bo + 64 * PADK * 2);
#pragma unroll
            for (int jo = 0; jo < 2; ++jo) {
                int j = jj * 2 + jo;
#pragma unroll
                for (int mi = 0; mi < 2; ++mi) {
                    mma16816(acc_g[mi][j], ah[mi], gh + jo * 2);
                    mma16816(acc_g[mi][j], ah[mi], gl + jo * 2);
                    mma16816(acc_g[mi][j], al[mi], gh + jo * 2);
                    mma16816(acc_u[mi][j], ah[mi], uh + jo * 2);
                    mma16816(acc_u[mi][j], ah[mi], ul + jo * 2);
                    mma16816(acc_u[mi][j], al[mi], uh + jo * 2);
                }
            }
        }
    }

    // epilogue (proven)
#pragma unroll
    for (int mi = 0; mi < 2; ++mi) {
#pragma unroll
        for (int j = 0; j < 4; ++j) {
            int row = m0 + wm * 32 + mi * 16 + (lid >> 2);
            int col = f0 + wn * 32 + j * 8 + (lid & 3) * 2;
#pragma unroll
            for (int half = 0; half < 2; ++half) {
                int r = row + half * 8;
                if (r < cnt) {
                    float g0 = acc_g[mi][j][half * 2 + 0];
                    float g1 = acc_g[mi][j][half * 2 + 1];
                    float u0 = acc_u[mi][j][half * 2 + 0];
                    float u1 = acc_u[mi][j][half * 2 + 1];
                    float h0 = u0 * g0 / (1.f + __expf(-g0));
                    float h1 = u1 * g1 / (1.f + __expf(-g1));
                    uint32_t hi, lo;
                    split2(h0, h1, &hi, &lo);
                    size_t o = (size_t)(base + r) * F_DIM + col;
                    *(uint32_t*)&g_H_hi[o] = hi;
                    *(uint32_t*)&g_H_lo[o] = lo;
                }
            }
        }
    }
}

// ---------------- GEMM2: O = H @ Wd ----------------
__global__ void __launch_bounds__(256) gemm2_mma(const float* __restrict__ wd) {
    int e = blockIdx.z;
    int cnt = g_cnt[e];
    int m0 = blockIdx.y * 128;
    if (m0 >= cnt) return;
    int base = g_off[e];
    int n0 = blockIdx.x * 128;

    __shared__ unsigned short As_h[2][128][PADK], As_l[2][128][PADK];
    __shared__ unsigned short Bs_h[2][128][PADK], Bs_l[2][128][PADK];

    int tid = threadIdx.x;
    int lid = tid & 31, wid = tid >> 5;
    int wm = wid >> 1, wn = wid & 1;

    uint32_t aH = smem_u32(As_h), aL = smem_u32(As_l);
    uint32_t bH = smem_u32(Bs_h), bL = smem_u32(Bs_l);

    int grp = lid >> 3, lr = lid & 7;
    uint32_t aofs = (uint32_t)(((wm * 32 + (grp & 1) * 8 + lr) * PADK + (grp >> 1) * 8) * 2);
    uint32_t bofs = (uint32_t)(((wn * 64 + (grp >> 1) * 8 + lr) * PADK + (grp & 1) * 8) * 2);

    float acc[2][8][4];
#pragma unroll
    for (int a = 0; a < 2; a++)
#pragma unroll
        for (int b = 0; b < 8; b++)
#pragma unroll
            for (int c = 0; c < 4; c++) acc[a][b][c] = 0.f;

    int row0 = tid >> 1, kh8 = (tid & 1) * 8;
    int am = m0 + row0;
    size_t arow = (size_t)(base + ((am < cnt) ? am : 0)) * F_DIM + kh8;
    const float* bsrc = wd + (size_t)e * F_DIM * D_DIM + (n0 + row0);

    uint4 aph[2], apl[2];
    float bpf[2][8];
    const int NS = F_DIM / 16;   // 32 stages

#pragma unroll
    for (int p = 0; p < 2; ++p) {
        int kp = p * 16;
        aph[p] = *(const uint4*)(g_H_hi + arow + kp);
        apl[p] = *(const uint4*)(g_H_lo + arow + kp);
#pragma unroll
        for (int j = 0; j < 8; ++j) bpf[p][j] = bsrc[(size_t)(kp + kh8 + j) * D_DIM];
    }

    for (int s = 0; s < NS; ++s) {
        int sl = s & 1;
        uint32_t bh4[4], bl4[4];
        split2(bpf[sl][0], bpf[sl][1], bh4 + 0, bl4 + 0);
        split2(bpf[sl][2], bpf[sl][3], bh4 + 1, bl4 + 1);
        split2(bpf[sl][4], bpf[sl][5], bh4 + 2, bl4 + 2);
        split2(bpf[sl][6], bpf[sl][7], bh4 + 3, bl4 + 3);
        *(uint4*)&As_h[sl][row0][kh8] = aph[sl];
        *(uint4*)&As_l[sl][row0][kh8] = apl[sl];
        *(uint4*)&Bs_h[sl][row0][kh8] = *(uint4*)bh4;
        *(uint4*)&Bs_l[sl][row0][kh8] = *(uint4*)bl4;
        __syncthreads();

        if (s + 2 < NS) {
            int kn = (s + 2) * 16;
            aph[sl] = *(const uint4*)(g_H_hi + arow + kn);
            apl[sl] = *(const uint4*)(g_H_lo + arow + kn);
#pragma unroll
            for (int j = 0; j < 8; ++j) bpf[sl][j] = bsrc[(size_t)(kn + kh8 + j) * D_DIM];
        }

        uint32_t bufo = (uint32_t)(sl * BUFB);
        uint32_t ah[2][4], al[2][4];
#pragma unroll
        for (int mi = 0; mi < 2; ++mi) {
            uint32_t ao = bufo + aofs + (uint32_t)(mi * 16 * PADK * 2);
            ldsm4(ah[mi], aH + ao);
            ldsm4(al[mi], aL + ao);
        }
#pragma unroll
        for (int jj = 0; jj < 4; ++jj) {
            uint32_t bo = bufo + bofs + (uint32_t)(jj * 16 * PADK * 2);
            uint32_t bh[4], bl[4];
            ldsm4(bh, bH + bo);
            ldsm4(bl, bL + bo);
#pragma unroll
            for (int jo = 0; jo < 2; ++jo) {
                int j = jj * 2 + jo;
#pragma unroll
                for (int mi = 0; mi < 2; ++mi) {
                    mma16816(acc[mi][j], ah[mi], bh + jo * 2);
                    mma16816(acc[mi][j], ah[mi], bl + jo * 2);
                    mma16816(acc[mi][j], al[mi], bh + jo * 2);
                }
            }
        }
    }

#pragma unroll
    for (int mi = 0; mi < 2; ++mi) {
#pragma unroll
        for (int j = 0; j < 8; ++j) {
            int row = m0 + wm * 32 + mi * 16 + (lid >> 2);
            int col = n0 + wn * 64 + j * 8 + (lid & 3) * 2;
#pragma unroll
            for (int half = 0; half < 2; ++half) {
                int r = row + half * 8;
                if (r < cnt) {
                    float2 v = make_float2(acc[mi][j][half * 2 + 0],
                                           acc[mi][j][half * 2 + 1]);
                    *(float2*)&g_O[(size_t)(base + r) * D_DIM + col] = v;
                }
            }
        }
    }
}

// ---------------- combine (proven) ----------------
__global__ void combine_kernel(float* __restrict__ out) {
    int idx = blockIdx.x * blockDim.x + threadIdx.x;
    int t = idx / (D_DIM / 4);
    int j4 = (idx % (D_DIM / 4)) * 4;
    float p0 = g_topk_p[t * 2 + 0];
    float p1 = g_topk_p[t * 2 + 1];
    int q0 = g_pair_pos[t * 2 + 0];
    int q1 = g_pair_pos[t * 2 + 1];
    float4 a = *(const float4*)(g_O + (size_t)q0 * D_DIM + j4);
    float4 b = *(const float4*)(g_O + (size_t)q1 * D_DIM + j4);
    float4 o;
    o.x = p0 * a.x + p1 * b.x;
    o.y = p0 * a.y + p1 * b.y;
    o.z = p0 * a.z + p1 * b.z;
    o.w = p0 * a.w + p1 * b.w;
    *(float4*)(out + (size_t)t * D_DIM + j4) = o;
}

extern "C" void kernel_launch(void* const* d_in, const int* in_sizes, int n_in,
                              void* d_out, int out_size) {
    const float* x  = (const float*)d_in[0];
    const float* wr = (const float*)d_in[1];
    const float* wg = (const float*)d_in[2];
    const float* wu = (const float*)d_in[3];
    const float* wd = (const float*)d_in[4];
    float* out = (float*)d_out;

    init_kernel<<<1, 32>>>();
    router_kernel<<<T_TOK, 128>>>(x, wr);
    prefix_kernel<<<1, 32>>>();
    scatter_kernel<<<T_TOK / 256, 256>>>();

    gemm1_mma<<<dim3(F_DIM / 64, NPAIR / 128, E_EXP), 256>>>(x, wg, wu);
    gemm2_mma<<<dim3(D_DIM / 128, NPAIR / 128, E_EXP), 256>>>(wd);

    combine_kernel<<<(T_TOK * D_DIM / 4) / 256, 256>>>(out);
}

// round 12
// speedup vs baseline: 1.3038x; 1.3038x over previous
#include <cuda_runtime.h>
#include <cuda_bf16.h>
#include <stdint.h>

#define T_TOK 8192
#define D_DIM 1024
#define E_EXP 8
#define F_DIM 512
#define NPAIR (T_TOK * 2)

// ---------------- device scratch (proven footprint ~101MB) ----------------
__device__ int   g_topk_idx[NPAIR];
__device__ float g_topk_p[NPAIR];
__device__ int   g_cnt[E_EXP];
__device__ int   g_off[E_EXP];
__device__ int   g_cur[E_EXP];
__device__ int   g_pair_token[NPAIR];
__device__ int   g_pair_pos[NPAIR];
__device__ __align__(256) __nv_bfloat16 g_H_hi[(size_t)(NPAIR + 128) * F_DIM];
__device__ __align__(256) __nv_bfloat16 g_H_lo[(size_t)(NPAIR + 128) * F_DIM];
__device__ float g_O[(size_t)NPAIR * D_DIM];

// ---------------- helpers ----------------
__device__ __forceinline__ uint32_t smem_u32(const void* p) {
    uint32_t a;
    asm("{ .reg .u64 t; cvta.to.shared.u64 t, %1; cvt.u32.u64 %0, t; }"
        : "=r"(a) : "l"(p));
    return a;
}
__device__ __forceinline__ void mma16816(float* c, const uint32_t* a, const uint32_t* b) {
    asm volatile(
        "mma.sync.aligned.m16n8k16.row.col.f32.bf16.bf16.f32 "
        "{%0,%1,%2,%3}, {%4,%5,%6,%7}, {%8,%9}, {%0,%1,%2,%3};"
        : "+f"(c[0]), "+f"(c[1]), "+f"(c[2]), "+f"(c[3])
        : "r"(a[0]), "r"(a[1]), "r"(a[2]), "r"(a[3]), "r"(b[0]), "r"(b[1]));
}
__device__ __forceinline__ void ldsm4(uint32_t* r, uint32_t addr) {
    asm volatile("ldmatrix.sync.aligned.m8n8.x4.shared.b16 {%0,%1,%2,%3}, [%4];"
        : "=r"(r[0]), "=r"(r[1]), "=r"(r[2]), "=r"(r[3]) : "r"(addr));
}
__device__ __forceinline__ void split2(float a, float b, uint32_t* hi, uint32_t* lo) {
    __nv_bfloat162 h = __float22bfloat162_rn(make_float2(a, b));
    float2 hf = __bfloat1622float2(h);
    __nv_bfloat162 l = __float22bfloat162_rn(make_float2(a - hf.x, b - hf.y));
    *hi = *reinterpret_cast<uint32_t*>(&h);
    *lo = *reinterpret_cast<uint32_t*>(&l);
}
__device__ __forceinline__ void split4(float4 v, uint32_t* hi2, uint32_t* lo2) {
    split2(v.x, v.y, hi2 + 0, lo2 + 0);
    split2(v.z, v.w, hi2 + 1, lo2 + 1);
}

// ---------------- small kernels (proven) ----------------
__global__ void init_kernel() {
    if (threadIdx.x < E_EXP) g_cnt[threadIdx.x] = 0;
}

__global__ void router_kernel(const float* __restrict__ x,
                              const float* __restrict__ wr) {
    int t = blockIdx.x;
    int tid = threadIdx.x;
    float acc[E_EXP];
#pragma unroll
    for (int e = 0; e < E_EXP; e++) acc[e] = 0.f;
    const float* xr = x + (size_t)t * D_DIM;
    for (int i = tid; i < D_DIM; i += 128) {
        float xv = xr[i];
#pragma unroll
        for (int e = 0; e < E_EXP; e++) acc[e] += xv * wr[e * D_DIM + i];
    }
    __shared__ float sh[E_EXP][128];
#pragma unroll
    for (int e = 0; e < E_EXP; e++) sh[e][tid] = acc[e];
    __syncthreads();
    for (int s = 64; s > 0; s >>= 1) {
        if (tid < s) {
#pragma unroll
            for (int e = 0; e < E_EXP; e++) sh[e][tid] += sh[e][tid + s];
        }
        __syncthreads();
    }
    if (tid == 0) {
        float l[E_EXP];
#pragma unroll
        for (int e = 0; e < E_EXP; e++) l[e] = sh[e][0];
        int i1 = 0;
#pragma unroll
        for (int e = 1; e < E_EXP; e++) if (l[e] > l[i1]) i1 = e;
        int i2 = (i1 == 0) ? 1 : 0;
#pragma unroll
        for (int e = 0; e < E_EXP; e++) if (e != i1 && l[e] > l[i2]) i2 = e;
        float ex = __expf(l[i2] - l[i1]);
        float inv = 1.f / (1.f + ex);
        g_topk_idx[t * 2 + 0] = i1; g_topk_p[t * 2 + 0] = inv;
        g_topk_idx[t * 2 + 1] = i2; g_topk_p[t * 2 + 1] = ex * inv;
        atomicAdd(&g_cnt[i1], 1);
        atomicAdd(&g_cnt[i2], 1);
    }
}

__global__ void prefix_kernel() {
    if (threadIdx.x == 0) {
        int acc = 0;
        for (int e = 0; e < E_EXP; e++) { g_off[e] = acc; g_cur[e] = acc; acc += g_cnt[e]; }
    }
}

__global__ void scatter_kernel() {
    int t = blockIdx.x * blockDim.x + threadIdx.x;
    if (t >= T_TOK) return;
#pragma unroll
    for (int k = 0; k < 2; k++) {
        int e = g_topk_idx[t * 2 + k];
        int pos = atomicAdd(&g_cur[e], 1);
        g_pair_token[pos] = t;
        g_pair_pos[t * 2 + k] = pos;
    }
}

// smem: 128 rows x 16 bf16 per K-stage, rows padded to 24 shorts, DOUBLE buffered.
// 4 arrays x [2][128][24] shorts = 49152 B (proven R10).
#define PADK 24
#define BUFB (128 * PADK * 2)

// ---------------- GEMM1: H = silu(X Wg) * (X Wu) ----------------
// R10 structure; distance-2 prefetch with COMPILE-TIME slot names (no dynamic
// register-array indexing -> no local-memory demotion).
__global__ void __launch_bounds__(256) gemm1_mma(const float* __restrict__ x,
                                                 const float* __restrict__ wg,
                                                 const float* __restrict__ wu) {
    int e = blockIdx.z;
    int cnt = g_cnt[e];
    int m0 = blockIdx.y * 128;
    if (m0 >= cnt) return;
    int base = g_off[e];
    int f0 = blockIdx.x * 64;

    __shared__ unsigned short As_h[2][128][PADK], As_l[2][128][PADK];
    __shared__ unsigned short Bs_h[2][128][PADK], Bs_l[2][128][PADK];

    int tid = threadIdx.x;
    int lid = tid & 31, wid = tid >> 5;
    int wm = wid >> 1, wn = wid & 1;

    uint32_t aH = smem_u32(As_h), aL = smem_u32(As_l);
    uint32_t bH = smem_u32(Bs_h), bL = smem_u32(Bs_l);

    int grp = lid >> 3, lr = lid & 7;
    uint32_t aofs = (uint32_t)(((wm * 32 + (grp & 1) * 8 + lr) * PADK + (grp >> 1) * 8) * 2);
    uint32_t bofs = (uint32_t)(((wn * 32 + (grp >> 1) * 8 + lr) * PADK + (grp & 1) * 8) * 2);

    float acc_g[2][4][4], acc_u[2][4][4];
#pragma unroll
    for (int a = 0; a < 2; a++)
#pragma unroll
        for (int b = 0; b < 4; b++)
#pragma unroll
            for (int c = 0; c < 4; c++) { acc_g[a][b][c] = 0.f; acc_u[a][b][c] = 0.f; }

    int row0 = tid >> 1, kh8 = (tid & 1) * 8;
    int am = m0 + row0;
    int mytok = g_pair_token[base + ((am < cnt) ? am : 0)];
    const float* asrc = x + (size_t)mytok * D_DIM + kh8;
    size_t eoff = (size_t)e * D_DIM * F_DIM;
    const float* bsrc = ((row0 < 64) ? wg : wu) + eoff + (f0 + (row0 & 63));

    const int NS = D_DIM / 16;   // 64 stages (even)

    // distance-2 prefetch: named slots (compile-time)
    float4 apf0_0, apf0_1, apf1_0, apf1_1;
    float  bpf0[8], bpf1[8];

    apf0_0 = *(const float4*)(asrc);
    apf0_1 = *(const float4*)(asrc + 4);
#pragma unroll
    for (int j = 0; j < 8; ++j) bpf0[j] = bsrc[(size_t)(kh8 + j) * F_DIM];
    apf1_0 = *(const float4*)(asrc + 16);
    apf1_1 = *(const float4*)(asrc + 16 + 4);
#pragma unroll
    for (int j = 0; j < 8; ++j) bpf1[j] = bsrc[(size_t)(16 + kh8 + j) * F_DIM];

#define G1_STAGE(SL, SIDX, APF0, APF1, BPF)                                        \
    do {                                                                           \
        uint32_t ah4[4], al4[4], bh4[4], bl4[4];                                   \
        split4(APF0, ah4 + 0, al4 + 0);                                            \
        split4(APF1, ah4 + 2, al4 + 2);                                            \
        split2(BPF[0], BPF[1], bh4 + 0, bl4 + 0);                                  \
        split2(BPF[2], BPF[3], bh4 + 1, bl4 + 1);                                  \
        split2(BPF[4], BPF[5], bh4 + 2, bl4 + 2);                                  \
        split2(BPF[6], BPF[7], bh4 + 3, bl4 + 3);                                  \
        *(uint4*)&As_h[SL][row0][kh8] = *(uint4*)ah4;                              \
        *(uint4*)&As_l[SL][row0][kh8] = *(uint4*)al4;                              \
        *(uint4*)&Bs_h[SL][row0][kh8] = *(uint4*)bh4;                              \
        *(uint4*)&Bs_l[SL][row0][kh8] = *(uint4*)bl4;                              \
        __syncthreads();                                                           \
        if ((SIDX) + 2 < NS) {                                                     \
            int kn = ((SIDX) + 2) * 16;                                            \
            APF0 = *(const float4*)(asrc + kn);                                    \
            APF1 = *(const float4*)(asrc + kn + 4);                                \
            _Pragma("unroll")                                                      \
            for (int j = 0; j < 8; ++j)                                            \
                BPF[j] = bsrc[(size_t)(kn + kh8 + j) * F_DIM];                     \
        }                                                                          \
        const uint32_t bufo = (uint32_t)((SL) * BUFB);                             \
        uint32_t ah[2][4], al[2][4];                                               \
        _Pragma("unroll")                                                          \
        for (int mi = 0; mi < 2; ++mi) {                                           \
            uint32_t ao = bufo + aofs + (uint32_t)(mi * 16 * PADK * 2);            \
            ldsm4(ah[mi], aH + ao);                                                \
            ldsm4(al[mi], aL + ao);                                                \
        }                                                                          \
        _Pragma("unroll")                                                          \
        for (int jj = 0; jj < 2; ++jj) {                                           \
            uint32_t bo = bufo + bofs + (uint32_t)(jj * 16 * PADK * 2);            \
            uint32_t gh[4], gl[4], uh[4], ul[4];                                   \
            ldsm4(gh, bH + bo);                                                    \
            ldsm4(gl, bL + bo);                                                    \
            ldsm4(uh, bH + bo + 64 * PADK * 2);                                    \
            ldsm4(ul, bL + bo + 64 * PADK * 2);                                    \
            _Pragma("unroll")                                                      \
            for (int jo = 0; jo < 2; ++jo) {                                       \
                int j = jj * 2 + jo;                                               \
                _Pragma("unroll")                                                  \
                for (int mi = 0; mi < 2; ++mi) {                                   \
                    mma16816(acc_g[mi][j], ah[mi], gh + jo * 2);                   \
                    mma16816(acc_g[mi][j], ah[mi], gl + jo * 2);                   \
                    mma16816(acc_g[mi][j], al[mi], gh + jo * 2);                   \
                    mma16816(acc_u[mi][j], ah[mi], uh + jo * 2);                   \
                    mma16816(acc_u[mi][j], ah[mi], ul + jo * 2);                   \
                    mma16816(acc_u[mi][j], al[mi], uh + jo * 2);                   \
                }                                                                  \
            }                                                                      \
        }                                                                          \
    } while (0)

    for (int s = 0; s < NS; s += 2) {
        G1_STAGE(0, s,     apf0_0, apf0_1, bpf0);
        G1_STAGE(1, s + 1, apf1_0, apf1_1, bpf1);
    }
#undef G1_STAGE

    // epilogue (proven)
#pragma unroll
    for (int mi = 0; mi < 2; ++mi) {
#pragma unroll
        for (int j = 0; j < 4; ++j) {
            int row = m0 + wm * 32 + mi * 16 + (lid >> 2);
            int col = f0 + wn * 32 + j * 8 + (lid & 3) * 2;
#pragma unroll
            for (int half = 0; half < 2; ++half) {
                int r = row + half * 8;
                if (r < cnt) {
                    float g0 = acc_g[mi][j][half * 2 + 0];
                    float g1 = acc_g[mi][j][half * 2 + 1];
                    float u0 = acc_u[mi][j][half * 2 + 0];
                    float u1 = acc_u[mi][j][half * 2 + 1];
                    float h0 = u0 * g0 / (1.f + __expf(-g0));
                    float h1 = u1 * g1 / (1.f + __expf(-g1));
                    uint32_t hi, lo;
                    split2(h0, h1, &hi, &lo);
                    size_t o = (size_t)(base + r) * F_DIM + col;
                    *(uint32_t*)&g_H_hi[o] = hi;
                    *(uint32_t*)&g_H_lo[o] = lo;
                }
            }
        }
    }
}

// ---------------- GEMM2: O = H @ Wd ----------------
__global__ void __launch_bounds__(256) gemm2_mma(const float* __restrict__ wd) {
    int e = blockIdx.z;
    int cnt = g_cnt[e];
    int m0 = blockIdx.y * 128;
    if (m0 >= cnt) return;
    int base = g_off[e];
    int n0 = blockIdx.x * 128;

    __shared__ unsigned short As_h[2][128][PADK], As_l[2][128][PADK];
    __shared__ unsigned short Bs_h[2][128][PADK], Bs_l[2][128][PADK];

    int tid = threadIdx.x;
    int lid = tid & 31, wid = tid >> 5;
    int wm = wid >> 1, wn = wid & 1;

    uint32_t aH = smem_u32(As_h), aL = smem_u32(As_l);
    uint32_t bH = smem_u32(Bs_h), bL = smem_u32(Bs_l);

    int grp = lid >> 3, lr = lid & 7;
    uint32_t aofs = (uint32_t)(((wm * 32 + (grp & 1) * 8 + lr) * PADK + (grp >> 1) * 8) * 2);
    uint32_t bofs = (uint32_t)(((wn * 64 + (grp >> 1) * 8 + lr) * PADK + (grp & 1) * 8) * 2);

    float acc[2][8][4];
#pragma unroll
    for (int a = 0; a < 2; a++)
#pragma unroll
        for (int b = 0; b < 8; b++)
#pragma unroll
            for (int c = 0; c < 4; c++) acc[a][b][c] = 0.f;

    int row0 = tid >> 1, kh8 = (tid & 1) * 8;
    int am = m0 + row0;
    size_t arow = (size_t)(base + ((am < cnt) ? am : 0)) * F_DIM + kh8;
    const float* bsrc = wd + (size_t)e * F_DIM * D_DIM + (n0 + row0);

    const int NS = F_DIM / 16;   // 32 stages (even)

    uint4 aph0, apl0, aph1, apl1;
    float bpf0[8], bpf1[8];

    aph0 = *(const uint4*)(g_H_hi + arow);
    apl0 = *(const uint4*)(g_H_lo + arow);
#pragma unroll
    for (int j = 0; j < 8; ++j) bpf0[j] = bsrc[(size_t)(kh8 + j) * D_DIM];
    aph1 = *(const uint4*)(g_H_hi + arow + 16);
    apl1 = *(const uint4*)(g_H_lo + arow + 16);
#pragma unroll
    for (int j = 0; j < 8; ++j) bpf1[j] = bsrc[(size_t)(16 + kh8 + j) * D_DIM];

#define G2_STAGE(SL, SIDX, APH, APL, BPF)                                          \
    do {                                                                           \
        uint32_t bh4[4], bl4[4];                                                   \
        split2(BPF[0], BPF[1], bh4 + 0, bl4 + 0);                                  \
        split2(BPF[2], BPF[3], bh4 + 1, bl4 + 1);                                  \
        split2(BPF[4], BPF[5], bh4 + 2, bl4 + 2);                                  \
        split2(BPF[6], BPF[7], bh4 + 3, bl4 + 3);                                  \
        *(uint4*)&As_h[SL][row0][kh8] = APH;                                       \
        *(uint4*)&As_l[SL][row0][kh8] = APL;                                       \
        *(uint4*)&Bs_h[SL][row0][kh8] = *(uint4*)bh4;                              \
        *(uint4*)&Bs_l[SL][row0][kh8] = *(uint4*)bl4;                              \
        __syncthreads();                                                           \
        if ((SIDX) + 2 < NS) {                                                     \
            int kn = ((SIDX) + 2) * 16;                                            \
            APH = *(const uint4*)(g_H_hi + arow + kn);                             \
            APL = *(const uint4*)(g_H_lo + arow + kn);                             \
            _Pragma("unroll")                                                      \
            for (int j = 0; j < 8; ++j)                                            \
                BPF[j] = bsrc[(size_t)(kn + kh8 + j) * D_DIM];                     \
        }                                                                          \
        const uint32_t bufo = (uint32_t)((SL) * BUFB);                             \
        uint32_t ah[2][4], al[2][4];                                               \
        _Pragma("unroll")                                                          \
        for (int mi = 0; mi < 2; ++mi) {                                           \
            uint32_t ao = bufo + aofs + (uint32_t)(mi * 16 * PADK * 2);            \
            ldsm4(ah[mi], aH + ao);                                                \
            ldsm4(al[mi], aL + ao);                                                \
        }                                                                          \
        _Pragma("unroll")                                                          \
        for (int jj = 0; jj < 4; ++jj) {                                           \
            uint32_t bo = bufo + bofs + (uint32_t)(jj * 16 * PADK * 2);            \
            uint32_t bh[4], bl[4];                                                 \
            ldsm4(bh, bH + bo);                                                    \
            ldsm4(bl, bL + bo);                                                    \
            _Pragma("unroll")                                                      \
            for (int jo = 0; jo < 2; ++jo) {                                       \
                int j = jj * 2 + jo;                                               \
                _Pragma("unroll")                                                  \
                for (int mi = 0; mi < 2; ++mi) {                                   \
                    mma16816(acc[mi][j], ah[mi], bh + jo * 2);                     \
                    mma16816(acc[mi][j], ah[mi], bl + jo * 2);                     \
                    mma16816(acc[mi][j], al[mi], bh + jo * 2);                     \
                }                                                                  \
            }                                                                      \
        }                                                                          \
    } while (0)

    for (int s = 0; s < NS; s += 2) {
        G2_STAGE(0, s,     aph0, apl0, bpf0);
        G2_STAGE(1, s + 1, aph1, apl1, bpf1);
    }
#undef G2_STAGE

#pragma unroll
    for (int mi = 0; mi < 2; ++mi) {
#pragma unroll
        for (int j = 0; j < 8; ++j) {
            int row = m0 + wm * 32 + mi * 16 + (lid >> 2);
            int col = n0 + wn * 64 + j * 8 + (lid & 3) * 2;
#pragma unroll
            for (int half = 0; half < 2; ++half) {
                int r = row + half * 8;
                if (r < cnt) {
                    float2 v = make_float2(acc[mi][j][half * 2 + 0],
                                           acc[mi][j][half * 2 + 1]);
                    *(float2*)&g_O[(size_t)(base + r) * D_DIM + col] = v;
                }
            }
        }
    }
}

// ---------------- combine (proven) ----------------
__global__ void combine_kernel(float* __restrict__ out) {
    int idx = blockIdx.x * blockDim.x + threadIdx.x;
    int t = idx / (D_DIM / 4);
    int j4 = (idx % (D_DIM / 4)) * 4;
    float p0 = g_topk_p[t * 2 + 0];
    float p1 = g_topk_p[t * 2 + 1];
    int q0 = g_pair_pos[t * 2 + 0];
    int q1 = g_pair_pos[t * 2 + 1];
    float4 a = *(const float4*)(g_O + (size_t)q0 * D_DIM + j4);
    float4 b = *(const float4*)(g_O + (size_t)q1 * D_DIM + j4);
    float4 o;
    o.x = p0 * a.x + p1 * b.x;
    o.y = p0 * a.y + p1 * b.y;
    o.z = p0 * a.z + p1 * b.z;
    o.w = p0 * a.w + p1 * b.w;
    *(float4*)(out + (size_t)t * D_DIM + j4) = o;
}

extern "C" void kernel_launch(void* const* d_in, const int* in_sizes, int n_in,
                              void* d_out, int out_size) {
    const float* x  = (const float*)d_in[0];
    const float* wr = (const float*)d_in[1];
    const float* wg = (const float*)d_in[2];
    const float* wu = (const float*)d_in[3];
    const float* wd = (const float*)d_in[4];
    float* out = (float*)d_out;

    init_kernel<<<1, 32>>>();
    router_kernel<<<T_TOK, 128>>>(x, wr);
    prefix_kernel<<<1, 32>>>();
    scatter_kernel<<<T_TOK / 256, 256>>>();

    gemm1_mma<<<dim3(F_DIM / 64, NPAIR / 128, E_EXP), 256>>>(x, wg, wu);
    gemm2_mma<<<dim3(D_DIM / 128, NPAIR / 128, E_EXP), 256>>>(wd);

    combine_kernel<<<(T_TOK * D_DIM / 4) / 256, 256>>>(out);
}

// round 13
// speedup vs baseline: 1.4309x; 1.0975x over previous
#include <cuda_runtime.h>
#include <cuda_bf16.h>
#include <stdint.h>

#define T_TOK 8192
#define D_DIM 1024
#define E_EXP 8
#define F_DIM 512
#define NPAIR (T_TOK * 2)

// ---------------- device scratch (proven footprint ~101MB) ----------------
__device__ int   g_topk_idx[NPAIR];
__device__ float g_topk_p[NPAIR];
__device__ int   g_cnt[E_EXP];
__device__ int   g_off[E_EXP];
__device__ int   g_cur[E_EXP];
__device__ int   g_pair_token[NPAIR];
__device__ int   g_pair_pos[NPAIR];
__device__ __align__(256) __nv_bfloat16 g_H_hi[(size_t)(NPAIR + 128) * F_DIM];
__device__ __align__(256) __nv_bfloat16 g_H_lo[(size_t)(NPAIR + 128) * F_DIM];
__device__ float g_O[(size_t)NPAIR * D_DIM];

// ---------------- helpers ----------------
__device__ __forceinline__ uint32_t smem_u32(const void* p) {
    uint32_t a;
    asm("{ .reg .u64 t; cvta.to.shared.u64 t, %1; cvt.u32.u64 %0, t; }"
        : "=r"(a) : "l"(p));
    return a;
}
__device__ __forceinline__ void mma16816(float* c, const uint32_t* a, const uint32_t* b) {
    asm volatile(
        "mma.sync.aligned.m16n8k16.row.col.f32.bf16.bf16.f32 "
        "{%0,%1,%2,%3}, {%4,%5,%6,%7}, {%8,%9}, {%0,%1,%2,%3};"
        : "+f"(c[0]), "+f"(c[1]), "+f"(c[2]), "+f"(c[3])
        : "r"(a[0]), "r"(a[1]), "r"(a[2]), "r"(a[3]), "r"(b[0]), "r"(b[1]));
}
__device__ __forceinline__ void ldsm4(uint32_t* r, uint32_t addr) {
    asm volatile("ldmatrix.sync.aligned.m8n8.x4.shared.b16 {%0,%1,%2,%3}, [%4];"
        : "=r"(r[0]), "=r"(r[1]), "=r"(r[2]), "=r"(r[3]) : "r"(addr));
}
__device__ __forceinline__ void ldsm4t(uint32_t* r, uint32_t addr) {
    asm volatile("ldmatrix.sync.aligned.m8n8.x4.trans.shared.b16 {%0,%1,%2,%3}, [%4];"
        : "=r"(r[0]), "=r"(r[1]), "=r"(r[2]), "=r"(r[3]) : "r"(addr));
}
__device__ __forceinline__ void split2(float a, float b, uint32_t* hi, uint32_t* lo) {
    __nv_bfloat162 h = __float22bfloat162_rn(make_float2(a, b));
    float2 hf = __bfloat1622float2(h);
    __nv_bfloat162 l = __float22bfloat162_rn(make_float2(a - hf.x, b - hf.y));
    *hi = *reinterpret_cast<uint32_t*>(&h);
    *lo = *reinterpret_cast<uint32_t*>(&l);
}
__device__ __forceinline__ void split4(float4 v, uint32_t* hi2, uint32_t* lo2) {
    split2(v.x, v.y, hi2 + 0, lo2 + 0);
    split2(v.z, v.w, hi2 + 1, lo2 + 1);
}

// ---------------- small kernels (proven) ----------------
__global__ void init_kernel() {
    if (threadIdx.x < E_EXP) g_cnt[threadIdx.x] = 0;
}

__global__ void router_kernel(const float* __restrict__ x,
                              const float* __restrict__ wr) {
    int t = blockIdx.x;
    int tid = threadIdx.x;
    float acc[E_EXP];
#pragma unroll
    for (int e = 0; e < E_EXP; e++) acc[e] = 0.f;
    const float* xr = x + (size_t)t * D_DIM;
    for (int i = tid; i < D_DIM; i += 128) {
        float xv = xr[i];
#pragma unroll
        for (int e = 0; e < E_EXP; e++) acc[e] += xv * wr[e * D_DIM + i];
    }
    __shared__ float sh[E_EXP][128];
#pragma unroll
    for (int e = 0; e < E_EXP; e++) sh[e][tid] = acc[e];
    __syncthreads();
    for (int s = 64; s > 0; s >>= 1) {
        if (tid < s) {
#pragma unroll
            for (int e = 0; e < E_EXP; e++) sh[e][tid] += sh[e][tid + s];
        }
        __syncthreads();
    }
    if (tid == 0) {
        float l[E_EXP];
#pragma unroll
        for (int e = 0; e < E_EXP; e++) l[e] = sh[e][0];
        int i1 = 0;
#pragma unroll
        for (int e = 1; e < E_EXP; e++) if (l[e] > l[i1]) i1 = e;
        int i2 = (i1 == 0) ? 1 : 0;
#pragma unroll
        for (int e = 0; e < E_EXP; e++) if (e != i1 && l[e] > l[i2]) i2 = e;
        float ex = __expf(l[i2] - l[i1]);
        float inv = 1.f / (1.f + ex);
        g_topk_idx[t * 2 + 0] = i1; g_topk_p[t * 2 + 0] = inv;
        g_topk_idx[t * 2 + 1] = i2; g_topk_p[t * 2 + 1] = ex * inv;
        atomicAdd(&g_cnt[i1], 1);
        atomicAdd(&g_cnt[i2], 1);
    }
}

__global__ void prefix_kernel() {
    if (threadIdx.x == 0) {
        int acc = 0;
        for (int e = 0; e < E_EXP; e++) { g_off[e] = acc; g_cur[e] = acc; acc += g_cnt[e]; }
    }
}

__global__ void scatter_kernel() {
    int t = blockIdx.x * blockDim.x + threadIdx.x;
    if (t >= T_TOK) return;
#pragma unroll
    for (int k = 0; k < 2; k++) {
        int e = g_topk_idx[t * 2 + k];
        int pos = atomicAdd(&g_cur[e], 1);
        g_pair_token[pos] = t;
        g_pair_pos[t * 2 + k] = pos;
    }
}

// A smem: [m][k] rows padded to 24 shorts, double buffered (proven R10).
// B smem: k-major [16][136] shorts, double buffered; row stride 272B = 68 words
// (68 mod 32 = 4 -> ldmatrix.trans phases hit all 32 banks once; proven in R9).
#define PADK 24
#define BPADB 136
#define BUFA (128 * PADK * 2)
#define BUFBB (16 * BPADB * 2)

// ---------------- GEMM1: H = silu(X Wg) * (X Wu) ----------------
__global__ void __launch_bounds__(256) gemm1_mma(const float* __restrict__ x,
                                                 const float* __restrict__ wg,
                                                 const float* __restrict__ wu) {
    int e = blockIdx.z;
    int cnt = g_cnt[e];
    int m0 = blockIdx.y * 128;
    if (m0 >= cnt) return;
    int base = g_off[e];
    int f0 = blockIdx.x * 64;

    __shared__ unsigned short As_h[2][128][PADK], As_l[2][128][PADK];
    __shared__ unsigned short Bs_h[2][16][BPADB], Bs_l[2][16][BPADB];

    int tid = threadIdx.x;
    int lid = tid & 31, wid = tid >> 5;
    int wm = wid >> 1, wn = wid & 1;

    uint32_t aH = smem_u32(As_h), aL = smem_u32(As_l);
    uint32_t bH = smem_u32(Bs_h), bL = smem_u32(Bs_l);

    int grp = lid >> 3, lr = lid & 7;
    uint32_t aofs = (uint32_t)(((wm * 32 + (grp & 1) * 8 + lr) * PADK + (grp >> 1) * 8) * 2);
    // B trans fragments (R9-proven): row k=(grp&1)*8+lr, col n=wn*32+(grp>>1)*8
    uint32_t bofs = (uint32_t)((((grp & 1) * 8 + lr) * BPADB + wn * 32 + (grp >> 1) * 8) * 2);

    float acc_g[2][4][4], acc_u[2][4][4];
#pragma unroll
    for (int a = 0; a < 2; a++)
#pragma unroll
        for (int b = 0; b < 4; b++)
#pragma unroll
            for (int c = 0; c < 4; c++) { acc_g[a][b][c] = 0.f; acc_u[a][b][c] = 0.f; }

    // A loads (proven R10): one smem row per thread, 8 k per half
    int row0 = tid >> 1, kh8 = (tid & 1) * 8;
    int am = m0 + row0;
    int mytok = g_pair_token[base + ((am < cnt) ? am : 0)];
    const float* asrc = x + (size_t)mytok * D_DIM + kh8;
    // B loads: coalesced along f. thread: k=tid>>4 (0..15), n=(tid&15)*8 (0..120)
    int bk = tid >> 4, bn = (tid & 15) * 8;
    size_t eoff = (size_t)e * D_DIM * F_DIM;
    const float* bsrc = ((bn < 64) ? wg : wu) + eoff + f0 + (bn & 63);

    float4 apf0, apf1, bv0, bv1;
    const int NS = D_DIM / 16;   // 64 stages

    apf0 = *(const float4*)(asrc);
    apf1 = *(const float4*)(asrc + 4);
    bv0 = *(const float4*)(bsrc + (size_t)bk * F_DIM);
    bv1 = *(const float4*)(bsrc + (size_t)bk * F_DIM + 4);

    for (int s = 0; s < NS; ++s) {
        int buf = s & 1;
        uint32_t ah4[4], al4[4], bh4[4], bl4[4];
        split4(apf0, ah4 + 0, al4 + 0);
        split4(apf1, ah4 + 2, al4 + 2);
        split4(bv0, bh4 + 0, bl4 + 0);
        split4(bv1, bh4 + 2, bl4 + 2);
        *(uint4*)&As_h[buf][row0][kh8] = *(uint4*)ah4;
        *(uint4*)&As_l[buf][row0][kh8] = *(uint4*)al4;
        *(uint4*)&Bs_h[buf][bk][bn] = *(uint4*)bh4;
        *(uint4*)&Bs_l[buf][bk][bn] = *(uint4*)bl4;
        __syncthreads();

        if (s + 1 < NS) {
            int kn = (s + 1) * 16;
            apf0 = *(const float4*)(asrc + kn);
            apf1 = *(const float4*)(asrc + kn + 4);
            bv0 = *(const float4*)(bsrc + (size_t)(kn + bk) * F_DIM);
            bv1 = *(const float4*)(bsrc + (size_t)(kn + bk) * F_DIM + 4);
        }

        uint32_t bufoA = (uint32_t)(buf * BUFA);
        uint32_t bufoB = (uint32_t)(buf * BUFBB);
        uint32_t ah[2][4], al[2][4];
#pragma unroll
        for (int mi = 0; mi < 2; ++mi) {
            uint32_t ao = bufoA + aofs + (uint32_t)(mi * 16 * PADK * 2);
            ldsm4(ah[mi], aH + ao);
            ldsm4(al[mi], aL + ao);
        }
#pragma unroll
        for (int jj = 0; jj < 2; ++jj) {
            uint32_t bo = bufoB + bofs + (uint32_t)(jj * 32);   // jj*16 cols * 2B
            uint32_t gh[4], gl[4], uh[4], ul[4];
            ldsm4t(gh, bH + bo);
            ldsm4t(gl, bL + bo);
            ldsm4t(uh, bH + bo + 128);   // up: +64 cols = +128B
            ldsm4t(ul, bL + bo + 128);
#pragma unroll
            for (int jo = 0; jo < 2; ++jo) {
                int j = jj * 2 + jo;
#pragma unroll
                for (int mi = 0; mi < 2; ++mi) {
                    mma16816(acc_g[mi][j], ah[mi], gh + jo * 2);
                    mma16816(acc_g[mi][j], ah[mi], gl + jo * 2);
                    mma16816(acc_g[mi][j], al[mi], gh + jo * 2);
                    mma16816(acc_u[mi][j], ah[mi], uh + jo * 2);
                    mma16816(acc_u[mi][j], ah[mi], ul + jo * 2);
                    mma16816(acc_u[mi][j], al[mi], uh + jo * 2);
                }
            }
        }
    }

    // epilogue (proven)
#pragma unroll
    for (int mi = 0; mi < 2; ++mi) {
#pragma unroll
        for (int j = 0; j < 4; ++j) {
            int row = m0 + wm * 32 + mi * 16 + (lid >> 2);
            int col = f0 + wn * 32 + j * 8 + (lid & 3) * 2;
#pragma unroll
            for (int half = 0; half < 2; ++half) {
                int r = row + half * 8;
                if (r < cnt) {
                    float g0 = acc_g[mi][j][half * 2 + 0];
                    float g1 = acc_g[mi][j][half * 2 + 1];
                    float u0 = acc_u[mi][j][half * 2 + 0];
                    float u1 = acc_u[mi][j][half * 2 + 1];
                    float h0 = u0 * g0 / (1.f + __expf(-g0));
                    float h1 = u1 * g1 / (1.f + __expf(-g1));
                    uint32_t hi, lo;
                    split2(h0, h1, &hi, &lo);
                    size_t o = (size_t)(base + r) * F_DIM + col;
                    *(uint32_t*)&g_H_hi[o] = hi;
                    *(uint32_t*)&g_H_lo[o] = lo;
                }
            }
        }
    }
}

// ---------------- GEMM2: O = H @ Wd (wd [e][f][d], d contiguous) ----------------
__global__ void __launch_bounds__(256) gemm2_mma(const float* __restrict__ wd) {
    int e = blockIdx.z;
    int cnt = g_cnt[e];
    int m0 = blockIdx.y * 128;
    if (m0 >= cnt) return;
    int base = g_off[e];
    int n0 = blockIdx.x * 128;

    __shared__ unsigned short As_h[2][128][PADK], As_l[2][128][PADK];
    __shared__ unsigned short Bs_h[2][16][BPADB], Bs_l[2][16][BPADB];

    int tid = threadIdx.x;
    int lid = tid & 31, wid = tid >> 5;
    int wm = wid >> 1, wn = wid & 1;

    uint32_t aH = smem_u32(As_h), aL = smem_u32(As_l);
    uint32_t bH = smem_u32(Bs_h), bL = smem_u32(Bs_l);

    int grp = lid >> 3, lr = lid & 7;
    uint32_t aofs = (uint32_t)(((wm * 32 + (grp & 1) * 8 + lr) * PADK + (grp >> 1) * 8) * 2);
    uint32_t bofs = (uint32_t)((((grp & 1) * 8 + lr) * BPADB + wn * 64 + (grp >> 1) * 8) * 2);

    float acc[2][8][4];
#pragma unroll
    for (int a = 0; a < 2; a++)
#pragma unroll
        for (int b = 0; b < 8; b++)
#pragma unroll
            for (int c = 0; c < 4; c++) acc[a][b][c] = 0.f;

    int row0 = tid >> 1, kh8 = (tid & 1) * 8;
    int am = m0 + row0;
    size_t arow = (size_t)(base + ((am < cnt) ? am : 0)) * F_DIM + kh8;
    int bk = tid >> 4, bn = (tid & 15) * 8;
    const float* bsrc = wd + (size_t)e * F_DIM * D_DIM + n0 + bn;

    uint4 aph, apl;
    float4 bv0, bv1;
    const int NS = F_DIM / 16;   // 32 stages

    aph = *(const uint4*)(g_H_hi + arow);
    apl = *(const uint4*)(g_H_lo + arow);
    bv0 = *(const float4*)(bsrc + (size_t)bk * D_DIM);
    bv1 = *(const float4*)(bsrc + (size_t)bk * D_DIM + 4);

    for (int s = 0; s < NS; ++s) {
        int buf = s & 1;
        uint32_t bh4[4], bl4[4];
        split4(bv0, bh4 + 0, bl4 + 0);
        split4(bv1, bh4 + 2, bl4 + 2);
        *(uint4*)&As_h[buf][row0][kh8] = aph;
        *(uint4*)&As_l[buf][row0][kh8] = apl;
        *(uint4*)&Bs_h[buf][bk][bn] = *(uint4*)bh4;
        *(uint4*)&Bs_l[buf][bk][bn] = *(uint4*)bl4;
        __syncthreads();

        if (s + 1 < NS) {
            int kn = (s + 1) * 16;
            aph = *(const uint4*)(g_H_hi + arow + kn);
            apl = *(const uint4*)(g_H_lo + arow + kn);
            bv0 = *(const float4*)(bsrc + (size_t)(kn + bk) * D_DIM);
            bv1 = *(const float4*)(bsrc + (size_t)(kn + bk) * D_DIM + 4);
        }

        uint32_t bufoA = (uint32_t)(buf * BUFA);
        uint32_t bufoB = (uint32_t)(buf * BUFBB);
        uint32_t ah[2][4], al[2][4];
#pragma unroll
        for (int mi = 0; mi < 2; ++mi) {
            uint32_t ao = bufoA + aofs + (uint32_t)(mi * 16 * PADK * 2);
            ldsm4(ah[mi], aH + ao);
            ldsm4(al[mi], aL + ao);
        }
#pragma unroll
        for (int jj = 0; jj < 4; ++jj) {
            uint32_t bo = bufoB + bofs + (uint32_t)(jj * 32);
            uint32_t bh[4], bl[4];
            ldsm4t(bh, bH + bo);
            ldsm4t(bl, bL + bo);
#pragma unroll
            for (int jo = 0; jo < 2; ++jo) {
                int j = jj * 2 + jo;
#pragma unroll
                for (int mi = 0; mi < 2; ++mi) {
                    mma16816(acc[mi][j], ah[mi], bh + jo * 2);
                    mma16816(acc[mi][j], ah[mi], bl + jo * 2);
                    mma16816(acc[mi][j], al[mi], bh + jo * 2);
                }
            }
        }
    }

#pragma unroll
    for (int mi = 0; mi < 2; ++mi) {
#pragma unroll
        for (int j = 0; j < 8; ++j) {
            int row = m0 + wm * 32 + mi * 16 + (lid >> 2);
            int col = n0 + wn * 64 + j * 8 + (lid & 3) * 2;
#pragma unroll
            for (int half = 0; half < 2; ++half) {
                int r = row + half * 8;
                if (r < cnt) {
                    float2 v = make_float2(acc[mi][j][half * 2 + 0],
                                           acc[mi][j][half * 2 + 1]);
                    *(float2*)&g_O[(size_t)(base + r) * D_DIM + col] = v;
                }
            }
        }
    }
}

// ---------------- combine (proven) ----------------
__global__ void combine_kernel(float* __restrict__ out) {
    int idx = blockIdx.x * blockDim.x + threadIdx.x;
    int t = idx / (D_DIM / 4);
    int j4 = (idx % (D_DIM / 4)) * 4;
    float p0 = g_topk_p[t * 2 + 0];
    float p1 = g_topk_p[t * 2 + 1];
    int q0 = g_pair_pos[t * 2 + 0];
    int q1 = g_pair_pos[t * 2 + 1];
    float4 a = *(const float4*)(g_O + (size_t)q0 * D_DIM + j4);
    float4 b = *(const float4*)(g_O + (size_t)q1 * D_DIM + j4);
    float4 o;
    o.x = p0 * a.x + p1 * b.x;
    o.y = p0 * a.y + p1 * b.y;
    o.z = p0 * a.z + p1 * b.z;
    o.w = p0 * a.w + p1 * b.w;
    *(float4*)(out + (size_t)t * D_DIM + j4) = o;
}

extern "C" void kernel_launch(void* const* d_in, const int* in_sizes, int n_in,
                              void* d_out, int out_size) {
    const float* x  = (const float*)d_in[0];
    const float* wr = (const float*)d_in[1];
    const float* wg = (const float*)d_in[2];
    const float* wu = (const float*)d_in[3];
    const float* wd = (const float*)d_in[4];
    float* out = (float*)d_out;

    init_kernel<<<1, 32>>>();
    router_kernel<<<T_TOK, 128>>>(x, wr);
    prefix_kernel<<<1, 32>>>();
    scatter_kernel<<<T_TOK / 256, 256>>>();

    gemm1_mma<<<dim3(F_DIM / 64, NPAIR / 128, E_EXP), 256>>>(x, wg, wu);
    gemm2_mma<<<dim3(D_DIM / 128, NPAIR / 128, E_EXP), 256>>>(wd);

    combine_kernel<<<(T_TOK * D_DIM / 4) / 256, 256>>>(out);
}

// round 14
// speedup vs baseline: 1.6945x; 1.1843x over previous
#include <cuda_runtime.h>
#include <cuda_fp16.h>
#include <stdint.h>

#define T_TOK 8192
#define D_DIM 1024
#define E_EXP 8
#define F_DIM 512
#define NPAIR (T_TOK * 2)

// ---------------- device scratch (proven footprint ~101MB) ----------------
__device__ int   g_topk_idx[NPAIR];
__device__ float g_topk_p[NPAIR];
__device__ int   g_cnt[E_EXP];
__device__ int   g_off[E_EXP];
__device__ int   g_cur[E_EXP];
__device__ int   g_pair_token[NPAIR];
__device__ int   g_pair_pos[NPAIR];
__device__ __align__(256) __half g_H_hi[(size_t)(NPAIR + 128) * F_DIM];
__device__ __align__(256) __half g_H_lo[(size_t)(NPAIR + 128) * F_DIM];
__device__ float g_O[(size_t)NPAIR * D_DIM];

// ---------------- helpers ----------------
__device__ __forceinline__ uint32_t smem_u32(const void* p) {
    uint32_t a;
    asm("{ .reg .u64 t; cvta.to.shared.u64 t, %1; cvt.u32.u64 %0, t; }"
        : "=r"(a) : "l"(p));
    return a;
}
// fp16 mma: D = A(f16) * B(f16) + C, fp32 accum
__device__ __forceinline__ void mma16816h(float* c, const uint32_t* a, const uint32_t* b) {
    asm volatile(
        "mma.sync.aligned.m16n8k16.row.col.f32.f16.f16.f32 "
        "{%0,%1,%2,%3}, {%4,%5,%6,%7}, {%8,%9}, {%0,%1,%2,%3};"
        : "+f"(c[0]), "+f"(c[1]), "+f"(c[2]), "+f"(c[3])
        : "r"(a[0]), "r"(a[1]), "r"(a[2]), "r"(a[3]), "r"(b[0]), "r"(b[1]));
}
__device__ __forceinline__ void ldsm4(uint32_t* r, uint32_t addr) {
    asm volatile("ldmatrix.sync.aligned.m8n8.x4.shared.b16 {%0,%1,%2,%3}, [%4];"
        : "=r"(r[0]), "=r"(r[1]), "=r"(r[2]), "=r"(r[3]) : "r"(addr));
}
__device__ __forceinline__ void ldsm4t(uint32_t* r, uint32_t addr) {
    asm volatile("ldmatrix.sync.aligned.m8n8.x4.trans.shared.b16 {%0,%1,%2,%3}, [%4];"
        : "=r"(r[0]), "=r"(r[1]), "=r"(r[2]), "=r"(r[3]) : "r"(addr));
}
// fp16 split: (a,b) -> hi half2 + lo half2 (residual)
__device__ __forceinline__ void split2h(float a, float b, uint32_t* hi, uint32_t* lo) {
    __half2 h = __floats2half2_rn(a, b);
    float2 hf = __half22float2(h);
    __half2 l = __floats2half2_rn(a - hf.x, b - hf.y);
    *hi = *reinterpret_cast<uint32_t*>(&h);
    *lo = *reinterpret_cast<uint32_t*>(&l);
}
__device__ __forceinline__ void split4h(float4 v, uint32_t* hi2, uint32_t* lo2) {
    split2h(v.x, v.y, hi2 + 0, lo2 + 0);
    split2h(v.z, v.w, hi2 + 1, lo2 + 1);
}
// plain fp16 convert (no split) for B
__device__ __forceinline__ uint32_t cvt2h(float a, float b) {
    __half2 h = __floats2half2_rn(a, b);
    return *reinterpret_cast<uint32_t*>(&h);
}

// ---------------- small kernels (proven) ----------------
__global__ void init_kernel() {
    if (threadIdx.x < E_EXP) g_cnt[threadIdx.x] = 0;
}

__global__ void router_kernel(const float* __restrict__ x,
                              const float* __restrict__ wr) {
    int t = blockIdx.x;
    int tid = threadIdx.x;
    float acc[E_EXP];
#pragma unroll
    for (int e = 0; e < E_EXP; e++) acc[e] = 0.f;
    const float* xr = x + (size_t)t * D_DIM;
    for (int i = tid; i < D_DIM; i += 128) {
        float xv = xr[i];
#pragma unroll
        for (int e = 0; e < E_EXP; e++) acc[e] += xv * wr[e * D_DIM + i];
    }
    __shared__ float sh[E_EXP][128];
#pragma unroll
    for (int e = 0; e < E_EXP; e++) sh[e][tid] = acc[e];
    __syncthreads();
    for (int s = 64; s > 0; s >>= 1) {
        if (tid < s) {
#pragma unroll
            for (int e = 0; e < E_EXP; e++) sh[e][tid] += sh[e][tid + s];
        }
        __syncthreads();
    }
    if (tid == 0) {
        float l[E_EXP];
#pragma unroll
        for (int e = 0; e < E_EXP; e++) l[e] = sh[e][0];
        int i1 = 0;
#pragma unroll
        for (int e = 1; e < E_EXP; e++) if (l[e] > l[i1]) i1 = e;
        int i2 = (i1 == 0) ? 1 : 0;
#pragma unroll
        for (int e = 0; e < E_EXP; e++) if (e != i1 && l[e] > l[i2]) i2 = e;
        float ex = __expf(l[i2] - l[i1]);
        float inv = 1.f / (1.f + ex);
        g_topk_idx[t * 2 + 0] = i1; g_topk_p[t * 2 + 0] = inv;
        g_topk_idx[t * 2 + 1] = i2; g_topk_p[t * 2 + 1] = ex * inv;
        atomicAdd(&g_cnt[i1], 1);
        atomicAdd(&g_cnt[i2], 1);
    }
}

__global__ void prefix_kernel() {
    if (threadIdx.x == 0) {
        int acc = 0;
        for (int e = 0; e < E_EXP; e++) { g_off[e] = acc; g_cur[e] = acc; acc += g_cnt[e]; }
    }
}

__global__ void scatter_kernel() {
    int t = blockIdx.x * blockDim.x + threadIdx.x;
    if (t >= T_TOK) return;
#pragma unroll
    for (int k = 0; k < 2; k++) {
        int e = g_topk_idx[t * 2 + k];
        int pos = atomicAdd(&g_cur[e], 1);
        g_pair_token[pos] = t;
        g_pair_pos[t * 2 + k] = pos;
    }
}

// A smem: [m][k] rows padded to 24 shorts, double buffered (proven R10/R13).
// B smem: k-major [16][136] shorts, double buffered (proven R13), hi only.
#define PADK 24
#define BPADB 136
#define BUFA (128 * PADK * 2)
#define BUFBB (16 * BPADB * 2)

// ---------------- GEMM1: H = silu(X Wg) * (X Wu), fp16 2-term ----------------
__global__ void __launch_bounds__(256) gemm1_mma(const float* __restrict__ x,
                                                 const float* __restrict__ wg,
                                                 const float* __restrict__ wu) {
    int e = blockIdx.z;
    int cnt = g_cnt[e];
    int m0 = blockIdx.y * 128;
    if (m0 >= cnt) return;
    int base = g_off[e];
    int f0 = blockIdx.x * 64;

    __shared__ unsigned short As_h[2][128][PADK], As_l[2][128][PADK];
    __shared__ unsigned short Bs_h[2][16][BPADB];

    int tid = threadIdx.x;
    int lid = tid & 31, wid = tid >> 5;
    int wm = wid >> 1, wn = wid & 1;

    uint32_t aH = smem_u32(As_h), aL = smem_u32(As_l);
    uint32_t bH = smem_u32(Bs_h);

    int grp = lid >> 3, lr = lid & 7;
    uint32_t aofs = (uint32_t)(((wm * 32 + (grp & 1) * 8 + lr) * PADK + (grp >> 1) * 8) * 2);
    uint32_t bofs = (uint32_t)((((grp & 1) * 8 + lr) * BPADB + wn * 32 + (grp >> 1) * 8) * 2);

    float acc_g[2][4][4], acc_u[2][4][4];
#pragma unroll
    for (int a = 0; a < 2; a++)
#pragma unroll
        for (int b = 0; b < 4; b++)
#pragma unroll
            for (int c = 0; c < 4; c++) { acc_g[a][b][c] = 0.f; acc_u[a][b][c] = 0.f; }

    int row0 = tid >> 1, kh8 = (tid & 1) * 8;
    int am = m0 + row0;
    int mytok = g_pair_token[base + ((am < cnt) ? am : 0)];
    const float* asrc = x + (size_t)mytok * D_DIM + kh8;
    int bk = tid >> 4, bn = (tid & 15) * 8;
    size_t eoff = (size_t)e * D_DIM * F_DIM;
    const float* bsrc = ((bn < 64) ? wg : wu) + eoff + f0 + (bn & 63);

    float4 apf0, apf1, bv0, bv1;
    const int NS = D_DIM / 16;   // 64 stages

    apf0 = *(const float4*)(asrc);
    apf1 = *(const float4*)(asrc + 4);
    bv0 = *(const float4*)(bsrc + (size_t)bk * F_DIM);
    bv1 = *(const float4*)(bsrc + (size_t)bk * F_DIM + 4);

    for (int s = 0; s < NS; ++s) {
        int buf = s & 1;
        uint32_t ah4[4], al4[4], bh4[4];
        split4h(apf0, ah4 + 0, al4 + 0);
        split4h(apf1, ah4 + 2, al4 + 2);
        bh4[0] = cvt2h(bv0.x, bv0.y);
        bh4[1] = cvt2h(bv0.z, bv0.w);
        bh4[2] = cvt2h(bv1.x, bv1.y);
        bh4[3] = cvt2h(bv1.z, bv1.w);
        *(uint4*)&As_h[buf][row0][kh8] = *(uint4*)ah4;
        *(uint4*)&As_l[buf][row0][kh8] = *(uint4*)al4;
        *(uint4*)&Bs_h[buf][bk][bn] = *(uint4*)bh4;
        __syncthreads();

        if (s + 1 < NS) {
            int kn = (s + 1) * 16;
            apf0 = *(const float4*)(asrc + kn);
            apf1 = *(const float4*)(asrc + kn + 4);
            bv0 = *(const float4*)(bsrc + (size_t)(kn + bk) * F_DIM);
            bv1 = *(const float4*)(bsrc + (size_t)(kn + bk) * F_DIM + 4);
        }

        uint32_t bufoA = (uint32_t)(buf * BUFA);
        uint32_t bufoB = (uint32_t)(buf * BUFBB);
        uint32_t ah[2][4], al[2][4];
#pragma unroll
        for (int mi = 0; mi < 2; ++mi) {
            uint32_t ao = bufoA + aofs + (uint32_t)(mi * 16 * PADK * 2);
            ldsm4(ah[mi], aH + ao);
            ldsm4(al[mi], aL + ao);
        }
#pragma unroll
        for (int jj = 0; jj < 2; ++jj) {
            uint32_t bo = bufoB + bofs + (uint32_t)(jj * 32);
            uint32_t gh[4], uh[4];
            ldsm4t(gh, bH + bo);
            ldsm4t(uh, bH + bo + 128);   // up: +64 cols
#pragma unroll
            for (int jo = 0; jo < 2; ++jo) {
                int j = jj * 2 + jo;
#pragma unroll
                for (int mi = 0; mi < 2; ++mi) {
                    mma16816h(acc_g[mi][j], ah[mi], gh + jo * 2);
                    mma16816h(acc_g[mi][j], al[mi], gh + jo * 2);
                    mma16816h(acc_u[mi][j], ah[mi], uh + jo * 2);
                    mma16816h(acc_u[mi][j], al[mi], uh + jo * 2);
                }
            }
        }
    }

    // epilogue: silu(g)*u, split into fp16 hi/lo H
#pragma unroll
    for (int mi = 0; mi < 2; ++mi) {
#pragma unroll
        for (int j = 0; j < 4; ++j) {
            int row = m0 + wm * 32 + mi * 16 + (lid >> 2);
            int col = f0 + wn * 32 + j * 8 + (lid & 3) * 2;
#pragma unroll
            for (int half = 0; half < 2; ++half) {
                int r = row + half * 8;
                if (r < cnt) {
                    float g0 = acc_g[mi][j][half * 2 + 0];
                    float g1 = acc_g[mi][j][half * 2 + 1];
                    float u0 = acc_u[mi][j][half * 2 + 0];
                    float u1 = acc_u[mi][j][half * 2 + 1];
                    float h0 = u0 * g0 / (1.f + __expf(-g0));
                    float h1 = u1 * g1 / (1.f + __expf(-g1));
                    uint32_t hi, lo;
                    split2h(h0, h1, &hi, &lo);
                    size_t o = (size_t)(base + r) * F_DIM + col;
                    *(uint32_t*)&g_H_hi[o] = hi;
                    *(uint32_t*)&g_H_lo[o] = lo;
                }
            }
        }
    }
}

// ---------------- GEMM2: O = H @ Wd, fp16 2-term ----------------
__global__ void __launch_bounds__(256) gemm2_mma(const float* __restrict__ wd) {
    int e = blockIdx.z;
    int cnt = g_cnt[e];
    int m0 = blockIdx.y * 128;
    if (m0 >= cnt) return;
    int base = g_off[e];
    int n0 = blockIdx.x * 128;

    __shared__ unsigned short As_h[2][128][PADK], As_l[2][128][PADK];
    __shared__ unsigned short Bs_h[2][16][BPADB];

    int tid = threadIdx.x;
    int lid = tid & 31, wid = tid >> 5;
    int wm = wid >> 1, wn = wid & 1;

    uint32_t aH = smem_u32(As_h), aL = smem_u32(As_l);
    uint32_t bH = smem_u32(Bs_h);

    int grp = lid >> 3, lr = lid & 7;
    uint32_t aofs = (uint32_t)(((wm * 32 + (grp & 1) * 8 + lr) * PADK + (grp >> 1) * 8) * 2);
    uint32_t bofs = (uint32_t)((((grp & 1) * 8 + lr) * BPADB + wn * 64 + (grp >> 1) * 8) * 2);

    float acc[2][8][4];
#pragma unroll
    for (int a = 0; a < 2; a++)
#pragma unroll
        for (int b = 0; b < 8; b++)
#pragma unroll
            for (int c = 0; c < 4; c++) acc[a][b][c] = 0.f;

    int row0 = tid >> 1, kh8 = (tid & 1) * 8;
    int am = m0 + row0;
    size_t arow = (size_t)(base + ((am < cnt) ? am : 0)) * F_DIM + kh8;
    int bk = tid >> 4, bn = (tid & 15) * 8;
    const float* bsrc = wd + (size_t)e * F_DIM * D_DIM + n0 + bn;

    uint4 aph, apl;
    float4 bv0, bv1;
    const int NS = F_DIM / 16;   // 32 stages

    aph = *(const uint4*)(g_H_hi + arow);
    apl = *(const uint4*)(g_H_lo + arow);
    bv0 = *(const float4*)(bsrc + (size_t)bk * D_DIM);
    bv1 = *(const float4*)(bsrc + (size_t)bk * D_DIM + 4);

    for (int s = 0; s < NS; ++s) {
        int buf = s & 1;
        uint32_t bh4[4];
        bh4[0] = cvt2h(bv0.x, bv0.y);
        bh4[1] = cvt2h(bv0.z, bv0.w);
        bh4[2] = cvt2h(bv1.x, bv1.y);
        bh4[3] = cvt2h(bv1.z, bv1.w);
        *(uint4*)&As_h[buf][row0][kh8] = aph;
        *(uint4*)&As_l[buf][row0][kh8] = apl;
        *(uint4*)&Bs_h[buf][bk][bn] = *(uint4*)bh4;
        __syncthreads();

        if (s + 1 < NS) {
            int kn = (s + 1) * 16;
            aph = *(const uint4*)(g_H_hi + arow + kn);
            apl = *(const uint4*)(g_H_lo + arow + kn);
            bv0 = *(const float4*)(bsrc + (size_t)(kn + bk) * D_DIM);
            bv1 = *(const float4*)(bsrc + (size_t)(kn + bk) * D_DIM + 4);
        }

        uint32_t bufoA = (uint32_t)(buf * BUFA);
        uint32_t bufoB = (uint32_t)(buf * BUFBB);
        uint32_t ah[2][4], al[2][4];
#pragma unroll
        for (int mi = 0; mi < 2; ++mi) {
            uint32_t ao = bufoA + aofs + (uint32_t)(mi * 16 * PADK * 2);
            ldsm4(ah[mi], aH + ao);
            ldsm4(al[mi], aL + ao);
        }
#pragma unroll
        for (int jj = 0; jj < 4; ++jj) {
            uint32_t bo = bufoB + bofs + (uint32_t)(jj * 32);
            uint32_t bh[4];
            ldsm4t(bh, bH + bo);
#pragma unroll
            for (int jo = 0; jo < 2; ++jo) {
                int j = jj * 2 + jo;
#pragma unroll
                for (int mi = 0; mi < 2; ++mi) {
                    mma16816h(acc[mi][j], ah[mi], bh + jo * 2);
                    mma16816h(acc[mi][j], al[mi], bh + jo * 2);
                }
            }
        }
    }

#pragma unroll
    for (int mi = 0; mi < 2; ++mi) {
#pragma unroll
        for (int j = 0; j < 8; ++j) {
            int row = m0 + wm * 32 + mi * 16 + (lid >> 2);
            int col = n0 + wn * 64 + j * 8 + (lid & 3) * 2;
#pragma unroll
            for (int half = 0; half < 2; ++half) {
                int r = row + half * 8;
                if (r < cnt) {
                    float2 v = make_float2(acc[mi][j][half * 2 + 0],
                                           acc[mi][j][half * 2 + 1]);
                    *(float2*)&g_O[(size_t)(base + r) * D_DIM + col] = v;
                }
            }
        }
    }
}

// ---------------- combine (proven) ----------------
__global__ void combine_kernel(float* __restrict__ out) {
    int idx = blockIdx.x * blockDim.x + threadIdx.x;
    int t = idx / (D_DIM / 4);
    int j4 = (idx % (D_DIM / 4)) * 4;
    float p0 = g_topk_p[t * 2 + 0];
    float p1 = g_topk_p[t * 2 + 1];
    int q0 = g_pair_pos[t * 2 + 0];
    int q1 = g_pair_pos[t * 2 + 1];
    float4 a = *(const float4*)(g_O + (size_t)q0 * D_DIM + j4);
    float4 b = *(const float4*)(g_O + (size_t)q1 * D_DIM + j4);
    float4 o;
    o.x = p0 * a.x + p1 * b.x;
    o.y = p0 * a.y + p1 * b.y;
    o.z = p0 * a.z + p1 * b.z;
    o.w = p0 * a.w + p1 * b.w;
    *(float4*)(out + (size_t)t * D_DIM + j4) = o;
}

extern "C" void kernel_launch(void* const* d_in, const int* in_sizes, int n_in,
                              void* d_out, int out_size) {
    const float* x  = (const float*)d_in[0];
    const float* wr = (const float*)d_in[1];
    const float* wg = (const float*)d_in[2];
    const float* wu = (const float*)d_in[3];
    const float* wd = (const float*)d_in[4];
    float* out = (float*)d_out;

    init_kernel<<<1, 32>>>();
    router_kernel<<<T_TOK, 128>>>(x, wr);
    prefix_kernel<<<1, 32>>>();
    scatter_kernel<<<T_TOK / 256, 256>>>();

    gemm1_mma<<<dim3(F_DIM / 64, NPAIR / 128, E_EXP), 256>>>(x, wg, wu);
    gemm2_mma<<<dim3(D_DIM / 128, NPAIR / 128, E_EXP), 256>>>(wd);

    combine_kernel<<<(T_TOK * D_DIM / 4) / 256, 256>>>(out);
}

// round 15
// speedup vs baseline: 2.3363x; 1.3787x over previous
#include <cuda_runtime.h>
#include <cuda_fp16.h>
#include <stdint.h>

#define T_TOK 8192
#define D_DIM 1024
#define E_EXP 8
#define F_DIM 512
#define NPAIR (T_TOK * 2)

// ---------------- device scratch (~84MB, within proven envelope) ----------------
__device__ int   g_topk_idx[NPAIR];
__device__ float g_topk_p[NPAIR];
__device__ int   g_cnt[E_EXP];
__device__ int   g_off[E_EXP];
__device__ int   g_cur[E_EXP];
__device__ int   g_pair_token[NPAIR];
__device__ int   g_pair_pos[NPAIR];
__device__ __align__(256) __half g_H[(size_t)(NPAIR + 128) * F_DIM];   // 16.5 MB
__device__ float g_O[(size_t)NPAIR * D_DIM];                           // 64 MB

// ---------------- helpers ----------------
__device__ __forceinline__ uint32_t smem_u32(const void* p) {
    uint32_t a;
    asm("{ .reg .u64 t; cvta.to.shared.u64 t, %1; cvt.u32.u64 %0, t; }"
        : "=r"(a) : "l"(p));
    return a;
}
// fp16 mma: D = A(f16) * B(f16) + C, fp32 accum
__device__ __forceinline__ void mma16816h(float* c, const uint32_t* a, const uint32_t* b) {
    asm volatile(
        "mma.sync.aligned.m16n8k16.row.col.f32.f16.f16.f32 "
        "{%0,%1,%2,%3}, {%4,%5,%6,%7}, {%8,%9}, {%0,%1,%2,%3};"
        : "+f"(c[0]), "+f"(c[1]), "+f"(c[2]), "+f"(c[3])
        : "r"(a[0]), "r"(a[1]), "r"(a[2]), "r"(a[3]), "r"(b[0]), "r"(b[1]));
}
__device__ __forceinline__ void ldsm4(uint32_t* r, uint32_t addr) {
    asm volatile("ldmatrix.sync.aligned.m8n8.x4.shared.b16 {%0,%1,%2,%3}, [%4];"
        : "=r"(r[0]), "=r"(r[1]), "=r"(r[2]), "=r"(r[3]) : "r"(addr));
}
__device__ __forceinline__ void ldsm4t(uint32_t* r, uint32_t addr) {
    asm volatile("ldmatrix.sync.aligned.m8n8.x4.trans.shared.b16 {%0,%1,%2,%3}, [%4];"
        : "=r"(r[0]), "=r"(r[1]), "=r"(r[2]), "=r"(r[3]) : "r"(addr));
}
// plain fp16 convert
__device__ __forceinline__ uint32_t cvt2h(float a, float b) {
    __half2 h = __floats2half2_rn(a, b);
    return *reinterpret_cast<uint32_t*>(&h);
}

// ---------------- small kernels (proven) ----------------
__global__ void init_kernel() {
    if (threadIdx.x < E_EXP) g_cnt[threadIdx.x] = 0;
}

__global__ void router_kernel(const float* __restrict__ x,
                              const float* __restrict__ wr) {
    int t = blockIdx.x;
    int tid = threadIdx.x;
    float acc[E_EXP];
#pragma unroll
    for (int e = 0; e < E_EXP; e++) acc[e] = 0.f;
    const float* xr = x + (size_t)t * D_DIM;
    for (int i = tid; i < D_DIM; i += 128) {
        float xv = xr[i];
#pragma unroll
        for (int e = 0; e < E_EXP; e++) acc[e] += xv * wr[e * D_DIM + i];
    }
    __shared__ float sh[E_EXP][128];
#pragma unroll
    for (int e = 0; e < E_EXP; e++) sh[e][tid] = acc[e];
    __syncthreads();
    for (int s = 64; s > 0; s >>= 1) {
        if (tid < s) {
#pragma unroll
            for (int e = 0; e < E_EXP; e++) sh[e][tid] += sh[e][tid + s];
        }
        __syncthreads();
    }
    if (tid == 0) {
        float l[E_EXP];
#pragma unroll
        for (int e = 0; e < E_EXP; e++) l[e] = sh[e][0];
        int i1 = 0;
#pragma unroll
        for (int e = 1; e < E_EXP; e++) if (l[e] > l[i1]) i1 = e;
        int i2 = (i1 == 0) ? 1 : 0;
#pragma unroll
        for (int e = 0; e < E_EXP; e++) if (e != i1 && l[e] > l[i2]) i2 = e;
        float ex = __expf(l[i2] - l[i1]);
        float inv = 1.f / (1.f + ex);
        g_topk_idx[t * 2 + 0] = i1; g_topk_p[t * 2 + 0] = inv;
        g_topk_idx[t * 2 + 1] = i2; g_topk_p[t * 2 + 1] = ex * inv;
        atomicAdd(&g_cnt[i1], 1);
        atomicAdd(&g_cnt[i2], 1);
    }
}

__global__ void prefix_kernel() {
    if (threadIdx.x == 0) {
        int acc = 0;
        for (int e = 0; e < E_EXP; e++) { g_off[e] = acc; g_cur[e] = acc; acc += g_cnt[e]; }
    }
}

__global__ void scatter_kernel() {
    int t = blockIdx.x * blockDim.x + threadIdx.x;
    if (t >= T_TOK) return;
#pragma unroll
    for (int k = 0; k < 2; k++) {
        int e = g_topk_idx[t * 2 + k];
        int pos = atomicAdd(&g_cur[e], 1);
        g_pair_token[pos] = t;
        g_pair_pos[t * 2 + k] = pos;
    }
}

// A smem: [m][k] rows padded to 24 shorts, double buffered (proven).
// B smem: k-major [16][136] shorts, double buffered (proven).
#define PADK 24
#define BPADB 136
#define BUFA (128 * PADK * 2)
#define BUFBB (16 * BPADB * 2)

// ---------------- GEMM1: H = silu(X Wg) * (X Wu), fp16 1-term ----------------
__global__ void __launch_bounds__(256) gemm1_mma(const float* __restrict__ x,
                                                 const float* __restrict__ wg,
                                                 const float* __restrict__ wu) {
    int e = blockIdx.z;
    int cnt = g_cnt[e];
    int m0 = blockIdx.y * 128;
    if (m0 >= cnt) return;
    int base = g_off[e];
    int f0 = blockIdx.x * 64;

    __shared__ unsigned short As_h[2][128][PADK];
    __shared__ unsigned short Bs_h[2][16][BPADB];

    int tid = threadIdx.x;
    int lid = tid & 31, wid = tid >> 5;
    int wm = wid >> 1, wn = wid & 1;

    uint32_t aH = smem_u32(As_h);
    uint32_t bH = smem_u32(Bs_h);

    int grp = lid >> 3, lr = lid & 7;
    uint32_t aofs = (uint32_t)(((wm * 32 + (grp & 1) * 8 + lr) * PADK + (grp >> 1) * 8) * 2);
    uint32_t bofs = (uint32_t)((((grp & 1) * 8 + lr) * BPADB + wn * 32 + (grp >> 1) * 8) * 2);

    float acc_g[2][4][4], acc_u[2][4][4];
#pragma unroll
    for (int a = 0; a < 2; a++)
#pragma unroll
        for (int b = 0; b < 4; b++)
#pragma unroll
            for (int c = 0; c < 4; c++) { acc_g[a][b][c] = 0.f; acc_u[a][b][c] = 0.f; }

    int row0 = tid >> 1, kh8 = (tid & 1) * 8;
    int am = m0 + row0;
    int mytok = g_pair_token[base + ((am < cnt) ? am : 0)];
    const float* asrc = x + (size_t)mytok * D_DIM + kh8;
    int bk = tid >> 4, bn = (tid & 15) * 8;
    size_t eoff = (size_t)e * D_DIM * F_DIM;
    const float* bsrc = ((bn < 64) ? wg : wu) + eoff + f0 + (bn & 63);

    float4 apf0, apf1, bv0, bv1;
    const int NS = D_DIM / 16;   // 64 stages

    apf0 = *(const float4*)(asrc);
    apf1 = *(const float4*)(asrc + 4);
    bv0 = *(const float4*)(bsrc + (size_t)bk * F_DIM);
    bv1 = *(const float4*)(bsrc + (size_t)bk * F_DIM + 4);

    for (int s = 0; s < NS; ++s) {
        int buf = s & 1;
        uint32_t ah4[4], bh4[4];
        ah4[0] = cvt2h(apf0.x, apf0.y);
        ah4[1] = cvt2h(apf0.z, apf0.w);
        ah4[2] = cvt2h(apf1.x, apf1.y);
        ah4[3] = cvt2h(apf1.z, apf1.w);
        bh4[0] = cvt2h(bv0.x, bv0.y);
        bh4[1] = cvt2h(bv0.z, bv0.w);
        bh4[2] = cvt2h(bv1.x, bv1.y);
        bh4[3] = cvt2h(bv1.z, bv1.w);
        *(uint4*)&As_h[buf][row0][kh8] = *(uint4*)ah4;
        *(uint4*)&Bs_h[buf][bk][bn] = *(uint4*)bh4;
        __syncthreads();

        if (s + 1 < NS) {
            int kn = (s + 1) * 16;
            apf0 = *(const float4*)(asrc + kn);
            apf1 = *(const float4*)(asrc + kn + 4);
            bv0 = *(const float4*)(bsrc + (size_t)(kn + bk) * F_DIM);
            bv1 = *(const float4*)(bsrc + (size_t)(kn + bk) * F_DIM + 4);
        }

        uint32_t bufoA = (uint32_t)(buf * BUFA);
        uint32_t bufoB = (uint32_t)(buf * BUFBB);
        uint32_t ah[2][4];
#pragma unroll
        for (int mi = 0; mi < 2; ++mi) {
            uint32_t ao = bufoA + aofs + (uint32_t)(mi * 16 * PADK * 2);
            ldsm4(ah[mi], aH + ao);
        }
#pragma unroll
        for (int jj = 0; jj < 2; ++jj) {
            uint32_t bo = bufoB + bofs + (uint32_t)(jj * 32);
            uint32_t gh[4], uh[4];
            ldsm4t(gh, bH + bo);
            ldsm4t(uh, bH + bo + 128);   // up: +64 cols
#pragma unroll
            for (int jo = 0; jo < 2; ++jo) {
                int j = jj * 2 + jo;
#pragma unroll
                for (int mi = 0; mi < 2; ++mi) {
                    mma16816h(acc_g[mi][j], ah[mi], gh + jo * 2);
                    mma16816h(acc_u[mi][j], ah[mi], uh + jo * 2);
                }
            }
        }
    }

    // epilogue: silu(g)*u, write fp16 H
#pragma unroll
    for (int mi = 0; mi < 2; ++mi) {
#pragma unroll
        for (int j = 0; j < 4; ++j) {
            int row = m0 + wm * 32 + mi * 16 + (lid >> 2);
            int col = f0 + wn * 32 + j * 8 + (lid & 3) * 2;
#pragma unroll
            for (int half = 0; half < 2; ++half) {
                int r = row + half * 8;
                if (r < cnt) {
                    float g0 = acc_g[mi][j][half * 2 + 0];
                    float g1 = acc_g[mi][j][half * 2 + 1];
                    float u0 = acc_u[mi][j][half * 2 + 0];
                    float u1 = acc_u[mi][j][half * 2 + 1];
                    float h0 = u0 * g0 / (1.f + __expf(-g0));
                    float h1 = u1 * g1 / (1.f + __expf(-g1));
                    size_t o = (size_t)(base + r) * F_DIM + col;
                    *(uint32_t*)&g_H[o] = cvt2h(h0, h1);
                }
            }
        }
    }
}

// ---------------- GEMM2: O = H @ Wd, fp16 1-term ----------------
__global__ void __launch_bounds__(256) gemm2_mma(const float* __restrict__ wd) {
    int e = blockIdx.z;
    int cnt = g_cnt[e];
    int m0 = blockIdx.y * 128;
    if (m0 >= cnt) return;
    int base = g_off[e];
    int n0 = blockIdx.x * 128;

    __shared__ unsigned short As_h[2][128][PADK];
    __shared__ unsigned short Bs_h[2][16][BPADB];

    int tid = threadIdx.x;
    int lid = tid & 31, wid = tid >> 5;
    int wm = wid >> 1, wn = wid & 1;

    uint32_t aH = smem_u32(As_h);
    uint32_t bH = smem_u32(Bs_h);

    int grp = lid >> 3, lr = lid & 7;
    uint32_t aofs = (uint32_t)(((wm * 32 + (grp & 1) * 8 + lr) * PADK + (grp >> 1) * 8) * 2);
    uint32_t bofs = (uint32_t)((((grp & 1) * 8 + lr) * BPADB + wn * 64 + (grp >> 1) * 8) * 2);

    float acc[2][8][4];
#pragma unroll
    for (int a = 0; a < 2; a++)
#pragma unroll
        for (int b = 0; b < 8; b++)
#pragma unroll
            for (int c = 0; c < 4; c++) acc[a][b][c] = 0.f;

    int row0 = tid >> 1, kh8 = (tid & 1) * 8;
    int am = m0 + row0;
    size_t arow = (size_t)(base + ((am < cnt) ? am : 0)) * F_DIM + kh8;
    int bk = tid >> 4, bn = (tid & 15) * 8;
    const float* bsrc = wd + (size_t)e * F_DIM * D_DIM + n0 + bn;

    uint4 aph;
    float4 bv0, bv1;
    const int NS = F_DIM / 16;   // 32 stages

    aph = *(const uint4*)(g_H + arow);
    bv0 = *(const float4*)(bsrc + (size_t)bk * D_DIM);
    bv1 = *(const float4*)(bsrc + (size_t)bk * D_DIM + 4);

    for (int s = 0; s < NS; ++s) {
        int buf = s & 1;
        uint32_t bh4[4];
        bh4[0] = cvt2h(bv0.x, bv0.y);
        bh4[1] = cvt2h(bv0.z, bv0.w);
        bh4[2] = cvt2h(bv1.x, bv1.y);
        bh4[3] = cvt2h(bv1.z, bv1.w);
        *(uint4*)&As_h[buf][row0][kh8] = aph;
        *(uint4*)&Bs_h[buf][bk][bn] = *(uint4*)bh4;
        __syncthreads();

        if (s + 1 < NS) {
            int kn = (s + 1) * 16;
            aph = *(const uint4*)(g_H + arow + kn);
            bv0 = *(const float4*)(bsrc + (size_t)(kn + bk) * D_DIM);
            bv1 = *(const float4*)(bsrc + (size_t)(kn + bk) * D_DIM + 4);
        }

        uint32_t bufoA = (uint32_t)(buf * BUFA);
        uint32_t bufoB = (uint32_t)(buf * BUFBB);
        uint32_t ah[2][4];
#pragma unroll
        for (int mi = 0; mi < 2; ++mi) {
            uint32_t ao = bufoA + aofs + (uint32_t)(mi * 16 * PADK * 2);
            ldsm4(ah[mi], aH + ao);
        }
#pragma unroll
        for (int jj = 0; jj < 4; ++jj) {
            uint32_t bo = bufoB + bofs + (uint32_t)(jj * 32);
            uint32_t bh[4];
            ldsm4t(bh, bH + bo);
#pragma unroll
            for (int jo = 0; jo < 2; ++jo) {
                int j = jj * 2 + jo;
#pragma unroll
                for (int mi = 0; mi < 2; ++mi) {
                    mma16816h(acc[mi][j], ah[mi], bh + jo * 2);
                }
            }
        }
    }

#pragma unroll
    for (int mi = 0; mi < 2; ++mi) {
#pragma unroll
        for (int j = 0; j < 8; ++j) {
            int row = m0 + wm * 32 + mi * 16 + (lid >> 2);
            int col = n0 + wn * 64 + j * 8 + (lid & 3) * 2;
#pragma unroll
            for (int half = 0; half < 2; ++half) {
                int r = row + half * 8;
                if (r < cnt) {
                    float2 v = make_float2(acc[mi][j][half * 2 + 0],
                                           acc[mi][j][half * 2 + 1]);
                    *(float2*)&g_O[(size_t)(base + r) * D_DIM + col] = v;
                }
            }
        }
    }
}

// ---------------- combine (proven) ----------------
__global__ void combine_kernel(float* __restrict__ out) {
    int idx = blockIdx.x * blockDim.x + threadIdx.x;
    int t = idx / (D_DIM / 4);
    int j4 = (idx % (D_DIM / 4)) * 4;
    float p0 = g_topk_p[t * 2 + 0];
    float p1 = g_topk_p[t * 2 + 1];
    int q0 = g_pair_pos[t * 2 + 0];
    int q1 = g_pair_pos[t * 2 + 1];
    float4 a = *(const float4*)(g_O + (size_t)q0 * D_DIM + j4);
    float4 b = *(const float4*)(g_O + (size_t)q1 * D_DIM + j4);
    float4 o;
    o.x = p0 * a.x + p1 * b.x;
    o.y = p0 * a.y + p1 * b.y;
    o.z = p0 * a.z + p1 * b.z;
    o.w = p0 * a.w + p1 * b.w;
    *(float4*)(out + (size_t)t * D_DIM + j4) = o;
}

extern "C" void kernel_launch(void* const* d_in, const int* in_sizes, int n_in,
                              void* d_out, int out_size) {
    const float* x  = (const float*)d_in[0];
    const float* wr = (const float*)d_in[1];
    const float* wg = (const float*)d_in[2];
    const float* wu = (const float*)d_in[3];
    const float* wd = (const float*)d_in[4];
    float* out = (float*)d_out;

    init_kernel<<<1, 32>>>();
    router_kernel<<<T_TOK, 128>>>(x, wr);
    prefix_kernel<<<1, 32>>>();
    scatter_kernel<<<T_TOK / 256, 256>>>();

    gemm1_mma<<<dim3(F_DIM / 64, NPAIR / 128, E_EXP), 256>>>(x, wg, wu);
    gemm2_mma<<<dim3(D_DIM / 128, NPAIR / 128, E_EXP), 256>>>(wd);

    combine_kernel<<<(T_TOK * D_DIM / 4) / 256, 256>>>(out);
}